// round 1
// baseline (speedup 1.0000x reference)
#include <cuda_runtime.h>

// Ragged segment mean:
//   out[b, d] = mean(seq[b, begin[b]:end[b], d])
// seq: [B=2048, L=512, D=512] fp32, begin/end: [B] int32, out: [B, D] fp32.
//
// One CTA per batch row. 128 threads; thread t owns float4 column t
// (D = 512 floats = 128 float4). Each row is a fully-coalesced 2048B read.
// Row loop unrolled x4 for memory-level parallelism.

#define B_DIM 2048
#define L_DIM 512
#define D_DIM 512
#define D_VEC (D_DIM / 4)   // 128 float4 per row

__global__ __launch_bounds__(D_VEC, 8)
void ragged_mean_kernel(const float* __restrict__ seq,
                        const int* __restrict__ begin,
                        const int* __restrict__ end,
                        float* __restrict__ out) {
    const int b   = blockIdx.x;
    const int tid = threadIdx.x;           // 0..127 -> float4 column

    const int s = begin[b];
    const int e = end[b];

    const float4* __restrict__ base =
        reinterpret_cast<const float4*>(seq) + (size_t)b * (L_DIM * D_VEC) + tid;

    float4 a0 = make_float4(0.f, 0.f, 0.f, 0.f);
    float4 a1 = make_float4(0.f, 0.f, 0.f, 0.f);

    int t = s;
    // Unrolled x4: 4 independent LDG.128 in flight per thread.
    for (; t + 4 <= e; t += 4) {
        float4 v0 = __ldg(base + (size_t)(t + 0) * D_VEC);
        float4 v1 = __ldg(base + (size_t)(t + 1) * D_VEC);
        float4 v2 = __ldg(base + (size_t)(t + 2) * D_VEC);
        float4 v3 = __ldg(base + (size_t)(t + 3) * D_VEC);
        // Pairwise into two accumulators to shorten the FADD dep chain.
        a0.x += v0.x + v1.x;  a0.y += v0.y + v1.y;
        a0.z += v0.z + v1.z;  a0.w += v0.w + v1.w;
        a1.x += v2.x + v3.x;  a1.y += v2.y + v3.y;
        a1.z += v2.z + v3.z;  a1.w += v2.w + v3.w;
    }
    for (; t < e; ++t) {
        float4 v = __ldg(base + (size_t)t * D_VEC);
        a0.x += v.x; a0.y += v.y; a0.z += v.z; a0.w += v.w;
    }

    const float inv = 1.0f / (float)(e - s);
    float4 r;
    r.x = (a0.x + a1.x) * inv;
    r.y = (a0.y + a1.y) * inv;
    r.z = (a0.z + a1.z) * inv;
    r.w = (a0.w + a1.w) * inv;

    reinterpret_cast<float4*>(out)[(size_t)b * D_VEC + tid] = r;
}

extern "C" void kernel_launch(void* const* d_in, const int* in_sizes, int n_in,
                              void* d_out, int out_size) {
    const float* seq   = (const float*)d_in[0];
    const int*   begin = (const int*)d_in[1];
    const int*   endp  = (const int*)d_in[2];
    float*       out   = (float*)d_out;

    ragged_mean_kernel<<<B_DIM, D_VEC>>>(seq, begin, endp, out);
}

// round 4
// speedup vs baseline: 1.0642x; 1.0642x over previous
#include <cuda_runtime.h>

// Ragged segment mean, split-L two-phase:
//   Phase 1: each (b, split) CTA sums rows {s+split, s+split+NS, ...} of
//            seq[b] into g_partial[b][split][:].  Strided interleave makes
//            the NS slices of one b differ by at most 1 row -> balanced.
//   Phase 2: out[b] = (sum of NS partials) / (e - s).
//
// seq: [B=2048, L=512, D=512] fp32, begin/end: [B] int32, out: [B, D] fp32.

#define B_DIM 2048
#define L_DIM 512
#define D_DIM 512
#define D_VEC (D_DIM / 4)   // 128 float4 per row
#define NS    4             // splits per batch row

__device__ float g_partial[(size_t)B_DIM * NS * D_DIM];

__global__ __launch_bounds__(D_VEC)
void ragged_partial_kernel(const float* __restrict__ seq,
                           const int* __restrict__ begin,
                           const int* __restrict__ end) {
    const int b     = blockIdx.x;
    const int split = blockIdx.y;
    const int tid   = threadIdx.x;         // 0..127 -> float4 column

    const int s = begin[b];
    const int e = end[b];

    const float4* __restrict__ base =
        reinterpret_cast<const float4*>(seq) + (size_t)b * (L_DIM * D_VEC) + tid;

    float4 a0 = make_float4(0.f, 0.f, 0.f, 0.f);
    float4 a1 = make_float4(0.f, 0.f, 0.f, 0.f);

    int t = s + split;
    // Unrolled x4 over the NS-strided row sequence: 4 independent LDG.128.
    for (; t + 3 * NS < e; t += 4 * NS) {
        float4 v0 = __ldg(base + (size_t)(t + 0 * NS) * D_VEC);
        float4 v1 = __ldg(base + (size_t)(t + 1 * NS) * D_VEC);
        float4 v2 = __ldg(base + (size_t)(t + 2 * NS) * D_VEC);
        float4 v3 = __ldg(base + (size_t)(t + 3 * NS) * D_VEC);
        a0.x += v0.x + v1.x;  a0.y += v0.y + v1.y;
        a0.z += v0.z + v1.z;  a0.w += v0.w + v1.w;
        a1.x += v2.x + v3.x;  a1.y += v2.y + v3.y;
        a1.z += v2.z + v3.z;  a1.w += v2.w + v3.w;
    }
    for (; t < e; t += NS) {
        float4 v = __ldg(base + (size_t)t * D_VEC);
        a0.x += v.x; a0.y += v.y; a0.z += v.z; a0.w += v.w;
    }

    float4 r;
    r.x = a0.x + a1.x;
    r.y = a0.y + a1.y;
    r.z = a0.z + a1.z;
    r.w = a0.w + a1.w;

    float4* part = reinterpret_cast<float4*>(g_partial);
    part[((size_t)b * NS + split) * D_VEC + tid] = r;
}

__global__ __launch_bounds__(D_VEC)
void ragged_reduce_kernel(const int* __restrict__ begin,
                          const int* __restrict__ end,
                          float* __restrict__ out) {
    const int b   = blockIdx.x;
    const int tid = threadIdx.x;

    const float4* part = reinterpret_cast<const float4*>(g_partial)
                         + (size_t)b * NS * D_VEC + tid;

    float4 p0 = part[0 * D_VEC];
    float4 p1 = part[1 * D_VEC];
    float4 p2 = part[2 * D_VEC];
    float4 p3 = part[3 * D_VEC];

    const float inv = 1.0f / (float)(end[b] - begin[b]);
    float4 r;
    r.x = ((p0.x + p1.x) + (p2.x + p3.x)) * inv;
    r.y = ((p0.y + p1.y) + (p2.y + p3.y)) * inv;
    r.z = ((p0.z + p1.z) + (p2.z + p3.z)) * inv;
    r.w = ((p0.w + p1.w) + (p2.w + p3.w)) * inv;

    reinterpret_cast<float4*>(out)[(size_t)b * D_VEC + tid] = r;
}

extern "C" void kernel_launch(void* const* d_in, const int* in_sizes, int n_in,
                              void* d_out, int out_size) {
    const float* seq   = (const float*)d_in[0];
    const int*   begin = (const int*)d_in[1];
    const int*   endp  = (const int*)d_in[2];
    float*       out   = (float*)d_out;

    dim3 grid1(B_DIM, NS);
    ragged_partial_kernel<<<grid1, D_VEC>>>(seq, begin, endp);
    ragged_reduce_kernel<<<B_DIM, D_VEC>>>(begin, endp, out);
}

// round 5
// speedup vs baseline: 1.0877x; 1.0221x over previous
#include <cuda_runtime.h>

// Ragged segment mean, fused split-L single kernel:
//   Each (b, split) CTA sums rows {s+split, s+split+NS, ...} of seq[b] into
//   g_partial[b][split][:] (strided interleave -> slices differ by <=1 row).
//   The LAST split CTA to finish for b (detected via g_count[b]) sums the NS
//   partials (L2-hot), divides by the segment length, writes out[b], and
//   resets g_count[b] to 0 so the kernel is graph-replay deterministic.
//
// seq: [B=2048, L=512, D=512] fp32, begin/end: [B] int32, out: [B, D] fp32.

#define B_DIM 2048
#define L_DIM 512
#define D_DIM 512
#define D_VEC (D_DIM / 4)   // 128 float4 per row
#define NS    4             // splits per batch row

__device__ float g_partial[(size_t)B_DIM * NS * D_DIM];
__device__ int   g_count[B_DIM];   // zero-initialized at load; reset each call

__global__ __launch_bounds__(D_VEC)
void ragged_mean_fused_kernel(const float* __restrict__ seq,
                              const int* __restrict__ begin,
                              const int* __restrict__ end,
                              float* __restrict__ out) {
    const int b     = blockIdx.x;
    const int split = blockIdx.y;
    const int tid   = threadIdx.x;         // 0..127 -> float4 column

    const int s = __ldg(begin + b);
    const int e = __ldg(end + b);

    const float4* __restrict__ base =
        reinterpret_cast<const float4*>(seq) + (size_t)b * (L_DIM * D_VEC) + tid;

    float4 a0 = make_float4(0.f, 0.f, 0.f, 0.f);
    float4 a1 = make_float4(0.f, 0.f, 0.f, 0.f);

    int t = s + split;
    // Unrolled x4 over the NS-strided row sequence: 4 independent LDG.128.
    for (; t + 3 * NS < e; t += 4 * NS) {
        float4 v0 = __ldg(base + (size_t)(t + 0 * NS) * D_VEC);
        float4 v1 = __ldg(base + (size_t)(t + 1 * NS) * D_VEC);
        float4 v2 = __ldg(base + (size_t)(t + 2 * NS) * D_VEC);
        float4 v3 = __ldg(base + (size_t)(t + 3 * NS) * D_VEC);
        a0.x += v0.x + v1.x;  a0.y += v0.y + v1.y;
        a0.z += v0.z + v1.z;  a0.w += v0.w + v1.w;
        a1.x += v2.x + v3.x;  a1.y += v2.y + v3.y;
        a1.z += v2.z + v3.z;  a1.w += v2.w + v3.w;
    }
    for (; t < e; t += NS) {
        float4 v = __ldg(base + (size_t)t * D_VEC);
        a0.x += v.x; a0.y += v.y; a0.z += v.z; a0.w += v.w;
    }

    float4 r;
    r.x = a0.x + a1.x;
    r.y = a0.y + a1.y;
    r.z = a0.z + a1.z;
    r.w = a0.w + a1.w;

    float4* part = reinterpret_cast<float4*>(g_partial) + (size_t)b * NS * D_VEC;
    part[(size_t)split * D_VEC + tid] = r;

    // Make the partial visible device-wide before signaling.
    __threadfence();

    __shared__ int is_last;
    if (tid == 0) {
        int prev = atomicAdd(&g_count[b], 1);
        is_last = (prev == NS - 1);
    }
    __syncthreads();

    if (is_last) {
        // Order the partial loads after the counter observation.
        __threadfence();

        float4 p0 = part[0 * D_VEC + tid];
        float4 p1 = part[1 * D_VEC + tid];
        float4 p2 = part[2 * D_VEC + tid];
        float4 p3 = part[3 * D_VEC + tid];

        const float inv = 1.0f / (float)(e - s);
        float4 o;
        o.x = ((p0.x + p1.x) + (p2.x + p3.x)) * inv;
        o.y = ((p0.y + p1.y) + (p2.y + p3.y)) * inv;
        o.z = ((p0.z + p1.z) + (p2.z + p3.z)) * inv;
        o.w = ((p0.w + p1.w) + (p2.w + p3.w)) * inv;

        reinterpret_cast<float4*>(out)[(size_t)b * D_VEC + tid] = o;

        if (tid == 0) g_count[b] = 0;   // reset for next graph replay
    }
}

extern "C" void kernel_launch(void* const* d_in, const int* in_sizes, int n_in,
                              void* d_out, int out_size) {
    const float* seq   = (const float*)d_in[0];
    const int*   begin = (const int*)d_in[1];
    const int*   endp  = (const int*)d_in[2];
    float*       out   = (float*)d_out;

    dim3 grid(B_DIM, NS);
    ragged_mean_fused_kernel<<<grid, D_VEC>>>(seq, begin, endp, out);
}